// round 1
// baseline (speedup 1.0000x reference)
#include <cuda_runtime.h>
#include <math.h>

#define LEAKY(v) ((v) > 0.f ? (v) : 0.01f * (v))

// ---------------- scratch (device globals; no allocation allowed) ----------------
__device__ float g_Weff[32 * 16 * 30];
__device__ float g_beff[32];
__device__ float g_pool1[64 * 32 * 811];   // after conv1+leaky+maxpool
__device__ float g_conv2[64 * 64 * 802];   // after conv2+leaky
__device__ float g_p0[64 * 64 * 300];      // adaptive pool bin=300
__device__ float g_p1[64 * 64 * 100];      // adaptive pool bin=100
__device__ float g_xc0[64 * 300 * 4];      // branch0 conv out, layout [b][t][4]
__device__ float g_xc1[64 * 100 * 4];      // branch1 conv out
__device__ float g_bo[64 * 2];             // per-branch linear outputs

// ---------------- K0: fold depthwise+pointwise into dense 16->32 conv ----------------
__global__ void k_weff(const float* __restrict__ w_dw, const float* __restrict__ b_dw,
                       const float* __restrict__ w_pw, const float* __restrict__ b_pw) {
    int idx = blockIdx.x * blockDim.x + threadIdx.x;
    if (idx < 32 * 16 * 30) {
        int k = idx % 30;
        int ci = (idx / 30) & 15;
        int o = idx / 480;
        float s = 0.f;
#pragma unroll
        for (int m = 0; m < 16; m++)
            s = fmaf(w_pw[o * 256 + ci * 16 + m], w_dw[(ci * 16 + m) * 30 + k], s);
        g_Weff[idx] = s;
    }
    if (idx < 32) {
        float s = b_pw[idx];
        for (int c = 0; c < 256; c++) s = fmaf(w_pw[idx * 256 + c], b_dw[c], s);
        g_beff[idx] = s;
    }
}

// ---------------- K1: fused conv1 (16->32, k=30) + bias + leaky + maxpool(20,5,ceil) ----------------
#define CONV1_LEN 4067
#define POOL1_LEN 811

__global__ __launch_bounds__(256) void k_conv1pool(const float* __restrict__ X) {
    extern __shared__ float smem[];
    float* sW = smem;                 // 32 * 481 (padded stride to kill bank conflicts)
    float* sX = sW + 32 * 481;        // 16 * 224
    float* sC = sX + 16 * 224;        // 32 * 192
    int tid = threadIdx.x;
    int b = blockIdx.y;
    int L0 = blockIdx.x * 32;         // pooled output tile start
    int Cb = L0 * 5;                  // conv position tile start

    for (int i = tid; i < 15360; i += 256) {
        int o = i / 480, r = i % 480;
        sW[o * 481 + r] = g_Weff[i];
    }
    const float* Xb = X + b * 16 * 4096;
    for (int i = tid; i < 16 * 224; i += 256) {
        int ci = i / 224, p = i % 224;
        int gp = Cb + p;
        sX[i] = (gp < 4096) ? Xb[ci * 4096 + gp] : 0.f;
    }
    __syncthreads();

    int oc = tid >> 3, g = tid & 7;
    float bias = g_beff[oc];
    for (int s = 0; s < 3; s++) {
        int base = (g + 8 * s) * 8;   // chunks g, g+8, g+16 -> 192 conv positions total
        float acc[8];
#pragma unroll
        for (int j = 0; j < 8; j++) acc[j] = bias;
        for (int ci = 0; ci < 16; ci++) {
            const float* xr = sX + ci * 224 + base;
            const float* wr = sW + oc * 481 + ci * 30;
            float xv[8];
#pragma unroll
            for (int j = 0; j < 8; j++) xv[j] = xr[j];
#pragma unroll
            for (int k = 0; k < 30; k++) {
                float w = wr[k];
#pragma unroll
                for (int j = 0; j < 8; j++) acc[j] = fmaf(w, xv[j], acc[j]);
#pragma unroll
                for (int j = 0; j < 7; j++) xv[j] = xv[j + 1];
                xv[7] = xr[k + 8];
            }
        }
#pragma unroll
        for (int j = 0; j < 8; j++) {
            int gp = Cb + base + j;
            float v = LEAKY(acc[j]);
            sC[oc * 192 + base + j] = (gp < CONV1_LEN) ? v : -INFINITY;  // ceil-mode -inf pad
        }
    }
    __syncthreads();

    // maxpool k=20 s=5 over the tile
    for (int i = tid; i < 1024; i += 256) {
        int l = i & 31, o = i >> 5;
        if (L0 + l < POOL1_LEN) {
            const float* c = sC + o * 192 + l * 5;
            float m = c[0];
#pragma unroll
            for (int t = 1; t < 20; t++) m = fmaxf(m, c[t]);
            g_pool1[(b * 32 + o) * POOL1_LEN + L0 + l] = m;
        }
    }
}

// ---------------- K2: conv2 (32->64, k=10) + bias + leaky ----------------
#define C2_IN 811
#define C2_OUT 802

__global__ __launch_bounds__(256) void k_conv2(const float* __restrict__ w_c2,
                                               const float* __restrict__ b_c2) {
    extern __shared__ float smem[];
    float* sW = smem;                 // 64 * 321 (padded)
    float* sX = sW + 64 * 321;        // 32 * 140
    int tid = threadIdx.x;
    int b = blockIdx.y;
    int T0 = blockIdx.x * 128;

    for (int i = tid; i < 64 * 320; i += 256) {
        int o = i / 320, r = i % 320;
        sW[o * 321 + r] = w_c2[i];
    }
    const float* Pb = g_pool1 + b * 32 * C2_IN;
    for (int i = tid; i < 32 * 140; i += 256) {
        int ci = i / 140, p = i % 140;
        int gp = T0 + p;
        sX[i] = (gp < C2_IN) ? Pb[ci * C2_IN + gp] : 0.f;
    }
    __syncthreads();

    int oc = tid >> 2, g = tid & 3;
    float bias = b_c2[oc];
    float* out = g_conv2 + (b * 64 + oc) * C2_OUT;
    for (int s = 0; s < 4; s++) {
        int base = (g + 4 * s) * 8;
        float acc[8];
#pragma unroll
        for (int j = 0; j < 8; j++) acc[j] = bias;
        for (int ci = 0; ci < 32; ci++) {
            const float* xr = sX + ci * 140 + base;
            const float* wr = sW + oc * 321 + ci * 10;
            float xv[8];
#pragma unroll
            for (int j = 0; j < 8; j++) xv[j] = xr[j];
#pragma unroll
            for (int k = 0; k < 10; k++) {
                float w = wr[k];
#pragma unroll
                for (int j = 0; j < 8; j++) acc[j] = fmaf(w, xv[j], acc[j]);
#pragma unroll
                for (int j = 0; j < 7; j++) xv[j] = xv[j + 1];
                xv[7] = xr[k + 8];
            }
        }
#pragma unroll
        for (int j = 0; j < 8; j++) {
            int gp = T0 + base + j;
            if (gp < C2_OUT) out[gp] = LEAKY(acc[j]);
        }
    }
}

// ---------------- K3: adaptive max pools (bin 300: k=204,s=2; bin 100: k=10,s=8) ----------------
__global__ __launch_bounds__(128) void k_adpool() {
    __shared__ float sR[802];
    __shared__ float sR2[401];
    int ch = blockIdx.x, b = blockIdx.y, tid = threadIdx.x;
    const float* row = g_conv2 + (b * 64 + ch) * 802;
    for (int i = tid; i < 802; i += 128) sR[i] = row[i];
    __syncthreads();
    for (int i = tid; i < 401; i += 128) sR2[i] = fmaxf(sR[2 * i], sR[2 * i + 1]);
    __syncthreads();
    // bin=300: window [2t, 2t+204) == pairs t..t+101
    for (int t = tid; t < 300; t += 128) {
        float m = -INFINITY;
        for (int u = 0; u < 102; u++) m = fmaxf(m, sR2[t + u]);
        g_p0[(b * 64 + ch) * 300 + t] = m;
    }
    // bin=100: window [8t, 8t+10)
    for (int t = tid; t < 100; t += 128) {
        float m = -INFINITY;
#pragma unroll
        for (int u = 0; u < 10; u++) m = fmaxf(m, sR[8 * t + u]);
        g_p1[(b * 64 + ch) * 100 + t] = m;
    }
}

// ---------------- K4: branch conv (64->4, k=3, pad=1) + leaky ----------------
__global__ __launch_bounds__(256) void k_smallconv(const float* __restrict__ wsc,
                                                   const float* __restrict__ bsc,
                                                   int branch) {
    extern __shared__ float sP[];  // 64 * T
    __shared__ float sw[768];
    const float* pooled = branch ? g_p1 : g_p0;
    float* xcout = branch ? g_xc1 : g_xc0;
    int T = branch ? 100 : 300;
    int b = blockIdx.x, tid = threadIdx.x;
    for (int i = tid; i < 768; i += 256) sw[i] = wsc[i];
    for (int i = tid; i < 64 * T; i += 256) sP[i] = pooled[b * 64 * T + i];
    __syncthreads();
    for (int i = tid; i < 4 * T; i += 256) {
        int t = i >> 2, oc = i & 3;
        float acc = bsc[oc];
        int k0 = (t == 0) ? 1 : 0;
        int k1 = (t == T - 1) ? 2 : 3;
        for (int ch = 0; ch < 64; ch++) {
            const float* pr = sP + ch * T + t - 1;
            const float* wr = sw + (oc * 64 + ch) * 3;
            for (int k = k0; k < k1; k++) acc = fmaf(wr[k], pr[k], acc);
        }
        xcout[(b * T + t) * 4 + oc] = LEAKY(acc);
    }
}

// ---------------- K5: LSTM (both branches) + final Linear(64->1) ----------------
__device__ __forceinline__ float sigm(float x) { return 1.f / (1.f + expf(-x)); }

__global__ __launch_bounds__(256) void k_lstm(
    const float* __restrict__ w_ih0, const float* __restrict__ b_ih0,
    const float* __restrict__ w_hh0, const float* __restrict__ b_hh0,
    const float* __restrict__ w_lin0, const float* __restrict__ b_lin0,
    const float* __restrict__ w_ih1, const float* __restrict__ b_ih1,
    const float* __restrict__ w_hh1, const float* __restrict__ b_hh1,
    const float* __restrict__ w_lin1, const float* __restrict__ b_lin1) {
    int blk = blockIdx.x;
    int br = blk >> 6, b = blk & 63;
    const float* wih = br ? w_ih1 : w_ih0;
    const float* bih = br ? b_ih1 : b_ih0;
    const float* whh = br ? w_hh1 : w_hh0;
    const float* bhh = br ? b_hh1 : b_hh0;
    const float* wl  = br ? w_lin1 : w_lin0;
    const float* bl  = br ? b_lin1 : b_lin0;
    const float* xc  = br ? g_xc1 : g_xc0;
    int T = br ? 100 : 300;

    __shared__ __align__(16) float sx[1200];
    __shared__ __align__(16) float sh[64];
    __shared__ float sg[256];
    int g = threadIdx.x;  // one thread per gate (i,f,g,o blocks of 64)

    float rw[64];
#pragma unroll
    for (int j = 0; j < 64; j++) rw[j] = whh[g * 64 + j];
    float ri0 = wih[g * 4 + 0], ri1 = wih[g * 4 + 1];
    float ri2 = wih[g * 4 + 2], ri3 = wih[g * 4 + 3];
    float bg = bih[g] + bhh[g];

    for (int i = g; i < T * 4; i += 256) sx[i] = xc[b * T * 4 + i];
    if (g < 64) sh[g] = 0.f;
    float c = 0.f;
    __syncthreads();

    const float4* sh4 = (const float4*)sh;
    const float4* sx4 = (const float4*)sx;
    for (int t = 0; t < T; t++) {
        float4 xv = sx4[t];
        // 4 independent accumulator chains to break FMA latency
        float a0 = bg, a1 = 0.f, a2 = 0.f, a3 = 0.f;
        a0 = fmaf(ri0, xv.x, a0);
        a1 = fmaf(ri1, xv.y, a1);
        a2 = fmaf(ri2, xv.z, a2);
        a3 = fmaf(ri3, xv.w, a3);
#pragma unroll
        for (int jq = 0; jq < 16; jq++) {
            float4 hv = sh4[jq];
            a0 = fmaf(rw[4 * jq + 0], hv.x, a0);
            a1 = fmaf(rw[4 * jq + 1], hv.y, a1);
            a2 = fmaf(rw[4 * jq + 2], hv.z, a2);
            a3 = fmaf(rw[4 * jq + 3], hv.w, a3);
        }
        sg[g] = (a0 + a1) + (a2 + a3);
        __syncthreads();
        if (g < 64) {
            float iv = sigm(sg[g]);
            float fv = sigm(sg[64 + g]);
            float gv = tanhf(sg[128 + g]);
            float ov = sigm(sg[192 + g]);
            c = fv * c + iv * gv;
            sh[g] = ov * tanhf(c);
        }
        __syncthreads();
    }
    if (g < 32) {
        float p = sh[g] * wl[g] + sh[g + 32] * wl[g + 32];
#pragma unroll
        for (int off = 16; off; off >>= 1) p += __shfl_down_sync(0xffffffffu, p, off);
        if (g == 0) g_bo[b * 2 + br] = p + bl[0];
    }
}

// ---------------- K6: final head Linear(2->1) + sigmoid ----------------
__global__ void k_final(const float* __restrict__ w_rul, const float* __restrict__ b_rul,
                        float* __restrict__ out) {
    int b = threadIdx.x;
    if (b < 64) {
        float z = fmaf(w_rul[0], g_bo[b * 2], fmaf(w_rul[1], g_bo[b * 2 + 1], b_rul[0]));
        out[b] = 1.f / (1.f + expf(-z));
    }
}

// ---------------- host launch ----------------
extern "C" void kernel_launch(void* const* d_in, const int* in_sizes, int n_in,
                              void* d_out, int out_size) {
    const float* X      = (const float*)d_in[0];
    const float* w_dw   = (const float*)d_in[1];
    const float* b_dw   = (const float*)d_in[2];
    const float* w_pw   = (const float*)d_in[3];
    const float* b_pw   = (const float*)d_in[4];
    const float* w_c2   = (const float*)d_in[5];
    const float* b_c2   = (const float*)d_in[6];
    const float* w_sc0  = (const float*)d_in[7];
    const float* b_sc0  = (const float*)d_in[8];
    const float* w_ih0  = (const float*)d_in[9];
    const float* b_ih0  = (const float*)d_in[10];
    const float* w_hh0  = (const float*)d_in[11];
    const float* b_hh0  = (const float*)d_in[12];
    const float* w_lin0 = (const float*)d_in[13];
    const float* b_lin0 = (const float*)d_in[14];
    const float* w_sc1  = (const float*)d_in[15];
    const float* b_sc1  = (const float*)d_in[16];
    const float* w_ih1  = (const float*)d_in[17];
    const float* b_ih1  = (const float*)d_in[18];
    const float* w_hh1  = (const float*)d_in[19];
    const float* b_hh1  = (const float*)d_in[20];
    const float* w_lin1 = (const float*)d_in[21];
    const float* b_lin1 = (const float*)d_in[22];
    const float* w_rul  = (const float*)d_in[23];
    const float* b_rul  = (const float*)d_in[24];
    float* out = (float*)d_out;

    size_t shB = (size_t)(32 * 481 + 16 * 224 + 32 * 192) * sizeof(float);  // 100480
    size_t shC = (size_t)(64 * 321 + 32 * 140) * sizeof(float);             //  99840+
    size_t shD = (size_t)(64 * 300) * sizeof(float);                        //  76800
    cudaFuncSetAttribute(k_conv1pool, cudaFuncAttributeMaxDynamicSharedMemorySize, (int)shB);
    cudaFuncSetAttribute(k_conv2, cudaFuncAttributeMaxDynamicSharedMemorySize, (int)shC);
    cudaFuncSetAttribute(k_smallconv, cudaFuncAttributeMaxDynamicSharedMemorySize, (int)shD);

    k_weff<<<60, 256>>>(w_dw, b_dw, w_pw, b_pw);
    k_conv1pool<<<dim3(26, 64), 256, shB>>>(X);
    k_conv2<<<dim3(7, 64), 256, shC>>>(w_c2, b_c2);
    k_adpool<<<dim3(64, 64), 128>>>();
    k_smallconv<<<64, 256, (size_t)(64 * 300) * sizeof(float)>>>(w_sc0, b_sc0, 0);
    k_smallconv<<<64, 256, (size_t)(64 * 100) * sizeof(float)>>>(w_sc1, b_sc1, 1);
    k_lstm<<<128, 256>>>(w_ih0, b_ih0, w_hh0, b_hh0, w_lin0, b_lin0,
                         w_ih1, b_ih1, w_hh1, b_hh1, w_lin1, b_lin1);
    k_final<<<1, 64>>>(w_rul, b_rul, out);
}

// round 2
// speedup vs baseline: 1.1909x; 1.1909x over previous
#include <cuda_runtime.h>
#include <math.h>

#define LEAKY(v) ((v) > 0.f ? (v) : 0.01f * (v))

typedef unsigned long long ull;

// ---- packed f32x2 helpers (Blackwell: ptxas never emits FFMA2 from C++) ----
__device__ __forceinline__ ull pack2(float lo, float hi) {
    ull r; asm("mov.b64 %0, {%1, %2};" : "=l"(r) : "f"(lo), "f"(hi)); return r;
}
__device__ __forceinline__ void unpack2(ull v, float& lo, float& hi) {
    asm("mov.b64 {%0, %1}, %2;" : "=f"(lo), "=f"(hi) : "l"(v));
}
__device__ __forceinline__ ull fma2(ull a, ull b, ull c) {
    ull d; asm("fma.rn.f32x2 %0, %1, %2, %3;" : "=l"(d) : "l"(a), "l"(b), "l"(c)); return d;
}
__device__ __forceinline__ ull add2(ull a, ull b) {
    ull d; asm("add.rn.f32x2 %0, %1, %2;" : "=l"(d) : "l"(a), "l"(b)); return d;
}

__device__ __forceinline__ float sigm_f(float x) { return 1.f / (1.f + __expf(-x)); }
__device__ __forceinline__ float tanh_f(float x) { return 2.f / (1.f + __expf(-2.f * x)) - 1.f; }

// ---------------- scratch ----------------
__device__ float g_Weff[32 * 16 * 30];
__device__ float g_beff[32];
__device__ float g_pool1[64 * 32 * 811];
__device__ float g_conv2[64 * 64 * 802];
__device__ float g_p0[64 * 64 * 300];
__device__ float g_p1[64 * 64 * 100];
__device__ float g_xc0[64 * 300 * 4];
__device__ float g_xc1[64 * 100 * 4];
__device__ float g_bo[64 * 2];

// ---------------- K0: fold depthwise+pointwise into dense 16->32 conv ----------------
__global__ void k_weff(const float* __restrict__ w_dw, const float* __restrict__ b_dw,
                       const float* __restrict__ w_pw, const float* __restrict__ b_pw) {
    int idx = blockIdx.x * blockDim.x + threadIdx.x;
    if (idx < 32 * 16 * 30) {
        int k = idx % 30;
        int ci = (idx / 30) & 15;
        int o = idx / 480;
        float s = 0.f;
#pragma unroll
        for (int m = 0; m < 16; m++)
            s = fmaf(w_pw[o * 256 + ci * 16 + m], w_dw[(ci * 16 + m) * 30 + k], s);
        g_Weff[idx] = s;
    }
    if (idx < 32) {
        float s = b_pw[idx];
        for (int c = 0; c < 256; c++) s = fmaf(w_pw[idx * 256 + c], b_dw[c], s);
        g_beff[idx] = s;
    }
}

// ---------------- K1: fused conv1 (16->32, k=30) + leaky + maxpool(20,5,ceil), FFMA2 ----------------
#define CONV1_LEN 4067
#define POOL1_LEN 811

__global__ __launch_bounds__(256, 2) void k_conv1pool(const float* __restrict__ X) {
    extern __shared__ float smem[];
    float* sW = smem;                 // 32 * 481
    float* sX = sW + 32 * 481;        // 16 * 224
    float* sC = sX + 16 * 224;        // 32 * 192
    int tid = threadIdx.x;
    int b = blockIdx.y;
    int L0 = blockIdx.x * 32;
    int Cb = L0 * 5;

    for (int i = tid; i < 15360; i += 256) {
        int o = i / 480, r = i % 480;
        sW[o * 481 + r] = g_Weff[i];
    }
    const float* Xb = X + b * 16 * 4096;
    for (int i = tid; i < 16 * 224; i += 256) {
        int ci = i / 224, p = i % 224;
        int gp = Cb + p;
        sX[i] = (gp < 4096) ? Xb[ci * 4096 + gp] : 0.f;
    }
    __syncthreads();

    // thread -> (oc pair, 12 positions)
    int pair = tid & 15, grp = tid >> 4;
    int oc = pair, oc2 = pair + 16;
    int base = grp * 12;

    ull bb = pack2(g_beff[oc], g_beff[oc2]);
    ull acc[12];
#pragma unroll
    for (int j = 0; j < 12; j++) acc[j] = bb;

    for (int ci = 0; ci < 16; ci++) {
        const float* xr = sX + ci * 224 + base;
        const float* wr  = sW + oc  * 481 + ci * 30;
        const float* wr2 = sW + oc2 * 481 + ci * 30;
        ull xd[12];
#pragma unroll
        for (int j = 0; j < 12; j++) { float xv = xr[j]; xd[j] = pack2(xv, xv); }
#pragma unroll
        for (int k = 0; k < 30; k++) {
            ull wp = pack2(wr[k], wr2[k]);
#pragma unroll
            for (int j = 0; j < 12; j++) acc[j] = fma2(wp, xd[j], acc[j]);
#pragma unroll
            for (int j = 0; j < 11; j++) xd[j] = xd[j + 1];
            float xn = xr[k + 12];
            xd[11] = pack2(xn, xn);
        }
    }
#pragma unroll
    for (int j = 0; j < 12; j++) {
        float v0, v1;
        unpack2(acc[j], v0, v1);
        int gp = Cb + base + j;
        bool ok = gp < CONV1_LEN;
        sC[oc  * 192 + base + j] = ok ? LEAKY(v0) : -INFINITY;
        sC[oc2 * 192 + base + j] = ok ? LEAKY(v1) : -INFINITY;
    }
    __syncthreads();

    for (int i = tid; i < 1024; i += 256) {
        int l = i & 31, o = i >> 5;
        if (L0 + l < POOL1_LEN) {
            const float* c = sC + o * 192 + l * 5;
            float m = c[0];
#pragma unroll
            for (int t = 1; t < 20; t++) m = fmaxf(m, c[t]);
            g_pool1[(b * 32 + o) * POOL1_LEN + L0 + l] = m;
        }
    }
}

// ---------------- K2: conv2 (32->64, k=10) + leaky, FFMA2 ----------------
#define C2_IN 811
#define C2_OUT 802

__global__ __launch_bounds__(256, 2) void k_conv2(const float* __restrict__ w_c2,
                                                  const float* __restrict__ b_c2) {
    extern __shared__ float smem[];
    float* sW = smem;                 // 64 * 321
    float* sX = sW + 64 * 321;        // 32 * 144
    int tid = threadIdx.x;
    int b = blockIdx.y;
    int T0 = blockIdx.x * 128;

    for (int i = tid; i < 64 * 320; i += 256) {
        int o = i / 320, r = i % 320;
        sW[o * 321 + r] = w_c2[i];
    }
    const float* Pb = g_pool1 + b * 32 * C2_IN;
    for (int i = tid; i < 32 * 144; i += 256) {
        int ci = i / 144, p = i % 144;
        int gp = T0 + p;
        sX[i] = (gp < C2_IN) ? Pb[ci * C2_IN + gp] : 0.f;
    }
    __syncthreads();

    int pair = tid & 31, grp = tid >> 5;     // 32 oc-pairs, 8 groups of 16 positions
    int oc = pair, oc2 = pair + 32;
    int base = grp * 16;

    ull bb = pack2(b_c2[oc], b_c2[oc2]);
    ull acc[16];
#pragma unroll
    for (int j = 0; j < 16; j++) acc[j] = bb;

    for (int ci = 0; ci < 32; ci++) {
        const float* xr = sX + ci * 144 + base;
        const float* wr  = sW + oc  * 321 + ci * 10;
        const float* wr2 = sW + oc2 * 321 + ci * 10;
        ull xd[16];
#pragma unroll
        for (int j = 0; j < 16; j++) { float xv = xr[j]; xd[j] = pack2(xv, xv); }
#pragma unroll
        for (int k = 0; k < 10; k++) {
            ull wp = pack2(wr[k], wr2[k]);
#pragma unroll
            for (int j = 0; j < 16; j++) acc[j] = fma2(wp, xd[j], acc[j]);
#pragma unroll
            for (int j = 0; j < 15; j++) xd[j] = xd[j + 1];
            float xn = xr[k + 16];
            xd[15] = pack2(xn, xn);
        }
    }
    float* out  = g_conv2 + (b * 64 + oc)  * C2_OUT;
    float* out2 = g_conv2 + (b * 64 + oc2) * C2_OUT;
#pragma unroll
    for (int j = 0; j < 16; j++) {
        int gp = T0 + base + j;
        if (gp < C2_OUT) {
            float v0, v1;
            unpack2(acc[j], v0, v1);
            out[gp]  = LEAKY(v0);
            out2[gp] = LEAKY(v1);
        }
    }
}

// ---------------- K3: adaptive max pools, van Herk for bin=300 ----------------
__global__ __launch_bounds__(128) void k_adpool() {
    __shared__ float sR[802];
    __shared__ float sR2[401];
    __shared__ float sP[401];   // prefix max within 102-chunks
    __shared__ float sS[401];   // suffix max within 102-chunks
    int ch = blockIdx.x, b = blockIdx.y, tid = threadIdx.x;
    const float* row = g_conv2 + (b * 64 + ch) * 802;
    for (int i = tid; i < 802; i += 128) sR[i] = row[i];
    __syncthreads();
    for (int i = tid; i < 401; i += 128) sR2[i] = fmaxf(sR[2 * i], sR[2 * i + 1]);
    __syncthreads();

    if (tid < 8) {
        int chunk = tid >> 1;
        int s0 = chunk * 102;
        int e = min(s0 + 102, 401);
        if (tid & 1) {
            float m = -INFINITY;
            for (int i = e - 1; i >= s0; --i) { m = fmaxf(m, sR2[i]); sS[i] = m; }
        } else {
            float m = -INFINITY;
            for (int i = s0; i < e; ++i) { m = fmaxf(m, sR2[i]); sP[i] = m; }
        }
    } else {
        // bin=100: window [8t, 8t+10) over sR (ready)
        for (int t = tid - 8; t < 100; t += 120) {
            float m = -INFINITY;
#pragma unroll
            for (int u = 0; u < 10; u++) m = fmaxf(m, sR[8 * t + u]);
            g_p1[(b * 64 + ch) * 100 + t] = m;
        }
    }
    __syncthreads();
    // bin=300: window = pairs [t, t+101] -> O(1) via chunked prefix/suffix
    for (int t = tid; t < 300; t += 128)
        g_p0[(b * 64 + ch) * 300 + t] = fmaxf(sS[t], sP[t + 101]);
}

// ---------------- K4: branch conv (64->4, k=3, pad=1) + leaky ----------------
__global__ __launch_bounds__(256) void k_smallconv(const float* __restrict__ wsc,
                                                   const float* __restrict__ bsc,
                                                   int branch) {
    extern __shared__ float sP[];  // 64 * T
    __shared__ float sw[768];
    const float* pooled = branch ? g_p1 : g_p0;
    float* xcout = branch ? g_xc1 : g_xc0;
    int T = branch ? 100 : 300;
    int b = blockIdx.x, tid = threadIdx.x;
    for (int i = tid; i < 768; i += 256) sw[i] = wsc[i];
    for (int i = tid; i < 64 * T; i += 256) sP[i] = pooled[b * 64 * T + i];
    __syncthreads();
    for (int i = tid; i < 4 * T; i += 256) {
        int t = i >> 2, oc = i & 3;
        float acc = bsc[oc];
        int k0 = (t == 0) ? 1 : 0;
        int k1 = (t == T - 1) ? 2 : 3;
        for (int ch = 0; ch < 64; ch++) {
            const float* pr = sP + ch * T + t - 1;
            const float* wr = sw + (oc * 64 + ch) * 3;
            for (int k = k0; k < k1; k++) acc = fmaf(wr[k], pr[k], acc);
        }
        xcout[(b * T + t) * 4 + oc] = LEAKY(acc);
    }
}

// ---------------- K5: LSTM, shuffle gate-exchange + double-buffered h, FFMA2 ----------------
__global__ __launch_bounds__(256) void k_lstm(
    const float* __restrict__ w_ih0, const float* __restrict__ b_ih0,
    const float* __restrict__ w_hh0, const float* __restrict__ b_hh0,
    const float* __restrict__ w_lin0, const float* __restrict__ b_lin0,
    const float* __restrict__ w_ih1, const float* __restrict__ b_ih1,
    const float* __restrict__ w_hh1, const float* __restrict__ b_hh1,
    const float* __restrict__ w_lin1, const float* __restrict__ b_lin1) {
    int blk = blockIdx.x;
    int br = blk >> 6, b = blk & 63;
    const float* wih = br ? w_ih1 : w_ih0;
    const float* bih = br ? b_ih1 : b_ih0;
    const float* whh = br ? w_hh1 : w_hh0;
    const float* bhh = br ? b_hh1 : b_hh0;
    const float* wl  = br ? w_lin1 : w_lin0;
    const float* bl  = br ? b_lin1 : b_lin0;
    const float* xc  = br ? g_xc1 : g_xc0;
    int T = br ? 100 : 300;

    __shared__ __align__(16) float sx[1200];
    __shared__ __align__(16) float sh[2][64];   // double buffer -> 1 barrier/step
    int tid = threadIdx.x;
    int u = tid >> 2, gt = tid & 3;             // unit, gate type (i,f,g,o)
    int r = gt * 64 + u;                        // weight row (PyTorch gate order)

    ull rw[32];
#pragma unroll
    for (int jp = 0; jp < 32; jp++) rw[jp] = pack2(whh[r * 64 + 2 * jp], whh[r * 64 + 2 * jp + 1]);
    ull ri01 = pack2(wih[r * 4 + 0], wih[r * 4 + 1]);
    ull ri23 = pack2(wih[r * 4 + 2], wih[r * 4 + 3]);
    ull bgp = pack2(bih[r] + bhh[r], 0.f);

    for (int i = tid; i < T * 4; i += 256) sx[i] = xc[b * T * 4 + i];
    if (tid < 64) sh[0][tid] = 0.f;
    float c = 0.f;
    __syncthreads();

    const ulonglong2* sx2 = (const ulonglong2*)sx;
    unsigned lane = tid & 31;
    unsigned bse = lane & ~3u;

    for (int t = 0; t < T; t++) {
        const ulonglong2* sh2 = (const ulonglong2*)sh[t & 1];
        ulonglong2 xv = sx2[t];
        ull a0 = fma2(ri01, xv.x, bgp);
        ull a1 = fma2(ri23, xv.y, 0ULL);
        ull a2 = 0ULL, a3 = 0ULL;
#pragma unroll
        for (int q = 0; q < 8; q++) {
            ulonglong2 hv = sh2[q];
            ulonglong2 hw = sh2[q + 8];
            a0 = fma2(rw[2 * q],      hv.x, a0);
            a1 = fma2(rw[2 * q + 1],  hv.y, a1);
            a2 = fma2(rw[2 * q + 16], hw.x, a2);
            a3 = fma2(rw[2 * q + 17], hw.y, a3);
        }
        ull s = add2(add2(a0, a1), add2(a2, a3));
        float lo, hi;
        unpack2(s, lo, hi);
        float a = lo + hi;
        float act = (gt == 2) ? tanh_f(a) : sigm_f(a);
        float vi = __shfl_sync(0xffffffffu, act, bse | 0);
        float vf = __shfl_sync(0xffffffffu, act, bse | 1);
        float vg = __shfl_sync(0xffffffffu, act, bse | 2);
        float vo = __shfl_sync(0xffffffffu, act, bse | 3);
        c = fmaf(vf, c, vi * vg);
        if (gt == 0) sh[(t + 1) & 1][u] = vo * tanh_f(c);
        __syncthreads();
    }
    const float* hf = sh[T & 1];
    if (tid < 32) {
        float p = hf[tid] * wl[tid] + hf[tid + 32] * wl[tid + 32];
#pragma unroll
        for (int off = 16; off; off >>= 1) p += __shfl_down_sync(0xffffffffu, p, off);
        if (tid == 0) g_bo[b * 2 + br] = p + bl[0];
    }
}

// ---------------- K6: final head ----------------
__global__ void k_final(const float* __restrict__ w_rul, const float* __restrict__ b_rul,
                        float* __restrict__ out) {
    int b = threadIdx.x;
    if (b < 64) {
        float z = fmaf(w_rul[0], g_bo[b * 2], fmaf(w_rul[1], g_bo[b * 2 + 1], b_rul[0]));
        out[b] = 1.f / (1.f + expf(-z));
    }
}

// ---------------- host launch ----------------
extern "C" void kernel_launch(void* const* d_in, const int* in_sizes, int n_in,
                              void* d_out, int out_size) {
    const float* X      = (const float*)d_in[0];
    const float* w_dw   = (const float*)d_in[1];
    const float* b_dw   = (const float*)d_in[2];
    const float* w_pw   = (const float*)d_in[3];
    const float* b_pw   = (const float*)d_in[4];
    const float* w_c2   = (const float*)d_in[5];
    const float* b_c2   = (const float*)d_in[6];
    const float* w_sc0  = (const float*)d_in[7];
    const float* b_sc0  = (const float*)d_in[8];
    const float* w_ih0  = (const float*)d_in[9];
    const float* b_ih0  = (const float*)d_in[10];
    const float* w_hh0  = (const float*)d_in[11];
    const float* b_hh0  = (const float*)d_in[12];
    const float* w_lin0 = (const float*)d_in[13];
    const float* b_lin0 = (const float*)d_in[14];
    const float* w_sc1  = (const float*)d_in[15];
    const float* b_sc1  = (const float*)d_in[16];
    const float* w_ih1  = (const float*)d_in[17];
    const float* b_ih1  = (const float*)d_in[18];
    const float* w_hh1  = (const float*)d_in[19];
    const float* b_hh1  = (const float*)d_in[20];
    const float* w_lin1 = (const float*)d_in[21];
    const float* b_lin1 = (const float*)d_in[22];
    const float* w_rul  = (const float*)d_in[23];
    const float* b_rul  = (const float*)d_in[24];
    float* out = (float*)d_out;

    size_t shB = (size_t)(32 * 481 + 16 * 224 + 32 * 192) * sizeof(float);
    size_t shC = (size_t)(64 * 321 + 32 * 144) * sizeof(float);
    size_t shD = (size_t)(64 * 300) * sizeof(float);
    cudaFuncSetAttribute(k_conv1pool, cudaFuncAttributeMaxDynamicSharedMemorySize, (int)shB);
    cudaFuncSetAttribute(k_conv2, cudaFuncAttributeMaxDynamicSharedMemorySize, (int)shC);
    cudaFuncSetAttribute(k_smallconv, cudaFuncAttributeMaxDynamicSharedMemorySize, (int)shD);

    k_weff<<<60, 256>>>(w_dw, b_dw, w_pw, b_pw);
    k_conv1pool<<<dim3(26, 64), 256, shB>>>(X);
    k_conv2<<<dim3(7, 64), 256, shC>>>(w_c2, b_c2);
    k_adpool<<<dim3(64, 64), 128>>>();
    k_smallconv<<<64, 256, (size_t)(64 * 300) * sizeof(float)>>>(w_sc0, b_sc0, 0);
    k_smallconv<<<64, 256, (size_t)(64 * 100) * sizeof(float)>>>(w_sc1, b_sc1, 1);
    k_lstm<<<128, 256>>>(w_ih0, b_ih0, w_hh0, b_hh0, w_lin0, b_lin0,
                         w_ih1, b_ih1, w_hh1, b_hh1, w_lin1, b_lin1);
    k_final<<<1, 64>>>(w_rul, b_rul, out);
}

// round 3
// speedup vs baseline: 1.1974x; 1.0054x over previous
#include <cuda_runtime.h>
#include <math.h>

#define LEAKY(v) ((v) > 0.f ? (v) : 0.01f * (v))

typedef unsigned long long ull;

// ---- packed f32x2 helpers ----
__device__ __forceinline__ ull pack2(float lo, float hi) {
    ull r; asm("mov.b64 %0, {%1, %2};" : "=l"(r) : "f"(lo), "f"(hi)); return r;
}
__device__ __forceinline__ void unpack2(ull v, float& lo, float& hi) {
    asm("mov.b64 {%0, %1}, %2;" : "=f"(lo), "=f"(hi) : "l"(v));
}
__device__ __forceinline__ ull fma2(ull a, ull b, ull c) {
    ull d; asm("fma.rn.f32x2 %0, %1, %2, %3;" : "=l"(d) : "l"(a), "l"(b), "l"(c)); return d;
}
__device__ __forceinline__ ull add2(ull a, ull b) {
    ull d; asm("add.rn.f32x2 %0, %1, %2;" : "=l"(d) : "l"(a), "l"(b)); return d;
}

__device__ __forceinline__ float sigm_f(float x) { return 1.f / (1.f + __expf(-x)); }
__device__ __forceinline__ float tanh_f(float x) { return 2.f / (1.f + __expf(-2.f * x)) - 1.f; }

// ---------------- scratch ----------------
__device__ ull   g_Wp1[16 * 480];          // conv1 weights packed (oc, oc+16)
__device__ float g_beff[32];
__device__ ull   g_Wp2[32 * 320];          // conv2 weights packed (oc, oc+32)
__device__ float g_pool1[64 * 32 * 811];
__device__ float g_conv2[64 * 64 * 802];
__device__ float g_p0[64 * 64 * 300];
__device__ float g_p1[64 * 64 * 100];
__device__ float g_xc0[64 * 300 * 4];
__device__ float g_xc1[64 * 100 * 4];
__device__ float g_bo[64 * 2];

// ---------------- K0: fold dw+pw into dense 16->32 conv, pre-packed pairs ----------------
__global__ void k_weff(const float* __restrict__ w_dw, const float* __restrict__ b_dw,
                       const float* __restrict__ w_pw, const float* __restrict__ b_pw,
                       const float* __restrict__ w_c2) {
    int idx = blockIdx.x * blockDim.x + threadIdx.x;
    if (idx < 16 * 480) {
        int k = idx % 30;
        int ci = (idx / 30) & 15;
        int pair = idx / 480;
        float s1 = 0.f, s2 = 0.f;
#pragma unroll
        for (int m = 0; m < 16; m++) {
            float wd = w_dw[(ci * 16 + m) * 30 + k];
            s1 = fmaf(w_pw[pair * 256 + ci * 16 + m], wd, s1);
            s2 = fmaf(w_pw[(pair + 16) * 256 + ci * 16 + m], wd, s2);
        }
        g_Wp1[pair * 480 + ci * 30 + k] = pack2(s1, s2);
    } else if (idx < 16 * 480 + 32 * 320) {
        int r = idx - 16 * 480;
        int pair = r / 320, rr = r % 320;
        g_Wp2[r] = pack2(w_c2[pair * 320 + rr], w_c2[(pair + 32) * 320 + rr]);
    }
    if (idx < 32) {
        float s = b_pw[idx];
        for (int c = 0; c < 256; c++) s = fmaf(w_pw[idx * 256 + c], b_dw[c], s);
        g_beff[idx] = s;
    }
}

// ---------------- K1: fused conv1 (16->32, k=30) + leaky + maxpool(20,5,ceil) ----------------
#define CONV1_LEN 4067
#define POOL1_LEN 811

__global__ __launch_bounds__(256, 2) void k_conv1pool(const float* __restrict__ X) {
    extern __shared__ ull smem_u[];
    ull* sWp = smem_u;                    // 16 * 481
    ull* sXd = sWp + 16 * 481;            // 16 * 208 (duplicated x)
    float* sC = (float*)(sXd + 16 * 208); // 32 * 177
    int tid = threadIdx.x;
    int b = blockIdx.y;
    int L0 = blockIdx.x * 32;
    int Cb = L0 * 5;

    for (int i = tid; i < 16 * 480; i += 256) {
        int pair = i / 480, r = i % 480;
        sWp[pair * 481 + r] = g_Wp1[i];
    }
    const float* Xb = X + b * 16 * 4096;
    for (int i = tid; i < 16 * 208; i += 256) {
        int ci = i / 208, p = i % 208;
        int gp = Cb + p;
        float v = (gp < 4096) ? Xb[ci * 4096 + gp] : 0.f;
        sXd[i] = pack2(v, v);
    }
    __syncthreads();

    int pair = tid & 15, grp = tid >> 4;
    int oc = pair, oc2 = pair + 16;
    int base = grp * 11;                  // 16 grps * 11 = 176 conv positions

    ull bb = pack2(g_beff[oc], g_beff[oc2]);
    ull acc[11];
#pragma unroll
    for (int j = 0; j < 11; j++) acc[j] = bb;

    for (int ci = 0; ci < 16; ci++) {
        const ull* xr = sXd + ci * 208 + base;
        const ull* wr = sWp + pair * 481 + ci * 30;
        ull xd[11];
#pragma unroll
        for (int j = 0; j < 11; j++) xd[j] = xr[j];
#pragma unroll
        for (int k = 0; k < 30; k++) {
            ull wp = wr[k];
#pragma unroll
            for (int j = 0; j < 11; j++) acc[j] = fma2(wp, xd[j], acc[j]);
#pragma unroll
            for (int j = 0; j < 10; j++) xd[j] = xd[j + 1];
            xd[10] = xr[k + 11];
        }
    }
#pragma unroll
    for (int j = 0; j < 11; j++) {
        float v0, v1;
        unpack2(acc[j], v0, v1);
        int gp = Cb + base + j;
        bool ok = gp < CONV1_LEN;
        sC[oc  * 177 + base + j] = ok ? LEAKY(v0) : -INFINITY;
        sC[oc2 * 177 + base + j] = ok ? LEAKY(v1) : -INFINITY;
    }
    __syncthreads();

    for (int i = tid; i < 1024; i += 256) {
        int l = i & 31, o = i >> 5;
        if (L0 + l < POOL1_LEN) {
            const float* c = sC + o * 177 + l * 5;
            float m = c[0];
#pragma unroll
            for (int t = 1; t < 20; t++) m = fmaxf(m, c[t]);
            g_pool1[(b * 32 + o) * POOL1_LEN + L0 + l] = m;
        }
    }
}

// ---------------- K2: conv2 (32->64, k=10) + leaky ----------------
#define C2_IN 811
#define C2_OUT 802

__global__ __launch_bounds__(256) void k_conv2(const float* __restrict__ b_c2) {
    extern __shared__ ull smem_u[];
    ull* sWp = smem_u;              // 32 * 321
    ull* sXd = sWp + 32 * 321;      // 32 * 138
    int tid = threadIdx.x;
    int b = blockIdx.y;
    int T0 = blockIdx.x * 128;

    for (int i = tid; i < 32 * 320; i += 256) {
        int pair = i / 320, r = i % 320;
        sWp[pair * 321 + r] = g_Wp2[i];
    }
    const float* Pb = g_pool1 + b * 32 * C2_IN;
    for (int i = tid; i < 32 * 138; i += 256) {
        int ci = i / 138, p = i % 138;
        int gp = T0 + p;
        float v = (gp < C2_IN) ? Pb[ci * C2_IN + gp] : 0.f;
        sXd[i] = pack2(v, v);
    }
    __syncthreads();

    int pair = tid & 31, grp = tid >> 5;   // 32 pairs, 8 grps of 16 positions
    int oc = pair, oc2 = pair + 32;
    int base = grp * 16;

    ull bb = pack2(b_c2[oc], b_c2[oc2]);
    ull acc[16];
#pragma unroll
    for (int j = 0; j < 16; j++) acc[j] = bb;

    for (int ci = 0; ci < 32; ci++) {
        const ull* xr = sXd + ci * 138 + base;
        const ull* wr = sWp + pair * 321 + ci * 10;
        ull xd[16];
#pragma unroll
        for (int j = 0; j < 16; j++) xd[j] = xr[j];
#pragma unroll
        for (int k = 0; k < 10; k++) {
            ull wp = wr[k];
#pragma unroll
            for (int j = 0; j < 16; j++) acc[j] = fma2(wp, xd[j], acc[j]);
#pragma unroll
            for (int j = 0; j < 15; j++) xd[j] = xd[j + 1];
            xd[15] = xr[k + 16];
        }
    }
    float* out  = g_conv2 + (b * 64 + oc)  * C2_OUT;
    float* out2 = g_conv2 + (b * 64 + oc2) * C2_OUT;
#pragma unroll
    for (int j = 0; j < 16; j++) {
        int gp = T0 + base + j;
        if (gp < C2_OUT) {
            float v0, v1;
            unpack2(acc[j], v0, v1);
            out[gp]  = LEAKY(v0);
            out2[gp] = LEAKY(v1);
        }
    }
}

// ---------------- K3: adaptive max pools, warp-scan van Herk for bin=300 ----------------
__global__ __launch_bounds__(128) void k_adpool() {
    __shared__ float sR[802];
    __shared__ float sR2[408];
    __shared__ float sP[408];
    __shared__ float sS[408];
    int ch = blockIdx.x, b = blockIdx.y, tid = threadIdx.x;
    int warp = tid >> 5, lane = tid & 31;
    const float* row = g_conv2 + (b * 64 + ch) * 802;
    for (int i = tid; i < 802; i += 128) sR[i] = row[i];
    __syncthreads();
    for (int i = tid; i < 408; i += 128) sR2[i] = (i < 401) ? fmaxf(sR[2 * i], sR[2 * i + 1]) : -INFINITY;
    __syncthreads();

    // chunked (102) prefix/suffix max scans; warp w owns chunk w
    {
        int s0 = warp * 102;
        int len = min(102, 401 - s0);
        float e[4];
#pragma unroll
        for (int j = 0; j < 4; j++) {
            int i = lane * 4 + j;
            e[j] = (i < len) ? sR2[s0 + i] : -INFINITY;
        }
        // prefix
        float lp0 = e[0], lp1 = fmaxf(lp0, e[1]), lp2 = fmaxf(lp1, e[2]), lp3 = fmaxf(lp2, e[3]);
        float incl = lp3;
#pragma unroll
        for (int d = 1; d < 32; d <<= 1) {
            float v = __shfl_up_sync(0xffffffffu, incl, d);
            if (lane >= d) incl = fmaxf(incl, v);
        }
        float excl = __shfl_up_sync(0xffffffffu, incl, 1);
        if (lane == 0) excl = -INFINITY;
        {
            int i = lane * 4;
            if (i     < len) sP[s0 + i]     = fmaxf(excl, lp0);
            if (i + 1 < len) sP[s0 + i + 1] = fmaxf(excl, lp1);
            if (i + 2 < len) sP[s0 + i + 2] = fmaxf(excl, lp2);
            if (i + 3 < len) sP[s0 + i + 3] = fmaxf(excl, lp3);
        }
        // suffix
        float ls3 = e[3], ls2 = fmaxf(e[2], ls3), ls1 = fmaxf(e[1], ls2), ls0 = fmaxf(e[0], ls1);
        float inclr = ls0;
#pragma unroll
        for (int d = 1; d < 32; d <<= 1) {
            float v = __shfl_down_sync(0xffffffffu, inclr, d);
            if (lane + d < 32) inclr = fmaxf(inclr, v);
        }
        float exclr = __shfl_down_sync(0xffffffffu, inclr, 1);
        if (lane == 31) exclr = -INFINITY;
        {
            int i = lane * 4;
            if (i     < len) sS[s0 + i]     = fmaxf(exclr, ls0);
            if (i + 1 < len) sS[s0 + i + 1] = fmaxf(exclr, ls1);
            if (i + 2 < len) sS[s0 + i + 2] = fmaxf(exclr, ls2);
            if (i + 3 < len) sS[s0 + i + 3] = fmaxf(exclr, ls3);
        }
    }
    __syncthreads();

    // bin=100: window [8t, 8t+10)
    if (tid < 100) {
        float m = -INFINITY;
#pragma unroll
        for (int u = 0; u < 10; u++) m = fmaxf(m, sR[8 * tid + u]);
        g_p1[(b * 64 + ch) * 100 + tid] = m;
    }
    // bin=300: window = pairs [t, t+101]
    for (int t = tid; t < 300; t += 128)
        g_p0[(b * 64 + ch) * 300 + t] = fmaxf(sS[t], sP[t + 101]);
}

// ---------------- K4: branch conv (64->4, k=3, pad=1) + leaky ----------------
__global__ __launch_bounds__(256) void k_smallconv(const float* __restrict__ wsc,
                                                   const float* __restrict__ bsc,
                                                   int branch) {
    extern __shared__ float sP[];  // 64 * T
    __shared__ float sw[768];
    const float* pooled = branch ? g_p1 : g_p0;
    float* xcout = branch ? g_xc1 : g_xc0;
    int T = branch ? 100 : 300;
    int b = blockIdx.x, tid = threadIdx.x;
    for (int i = tid; i < 768; i += 256) sw[i] = wsc[i];
    for (int i = tid; i < 64 * T; i += 256) sP[i] = pooled[b * 64 * T + i];
    __syncthreads();
    for (int i = tid; i < 4 * T; i += 256) {
        int t = i >> 2, oc = i & 3;
        float acc = bsc[oc];
        int k0 = (t == 0) ? 1 : 0;
        int k1 = (t == T - 1) ? 2 : 3;
        for (int ch = 0; ch < 64; ch++) {
            const float* pr = sP + ch * T + t - 1;
            const float* wr = sw + (oc * 64 + ch) * 3;
            for (int k = k0; k < k1; k++) acc = fmaf(wr[k], pr[k], acc);
        }
        xcout[(b * T + t) * 4 + oc] = LEAKY(acc);
    }
}

// ---------------- K5: LSTM, shuffle gate-exchange + double-buffered h, FFMA2 ----------------
__global__ __launch_bounds__(256) void k_lstm(
    const float* __restrict__ w_ih0, const float* __restrict__ b_ih0,
    const float* __restrict__ w_hh0, const float* __restrict__ b_hh0,
    const float* __restrict__ w_lin0, const float* __restrict__ b_lin0,
    const float* __restrict__ w_ih1, const float* __restrict__ b_ih1,
    const float* __restrict__ w_hh1, const float* __restrict__ b_hh1,
    const float* __restrict__ w_lin1, const float* __restrict__ b_lin1) {
    int blk = blockIdx.x;
    int br = blk >> 6, b = blk & 63;
    const float* wih = br ? w_ih1 : w_ih0;
    const float* bih = br ? b_ih1 : b_ih0;
    const float* whh = br ? w_hh1 : w_hh0;
    const float* bhh = br ? b_hh1 : b_hh0;
    const float* wl  = br ? w_lin1 : w_lin0;
    const float* bl  = br ? b_lin1 : b_lin0;
    const float* xc  = br ? g_xc1 : g_xc0;
    int T = br ? 100 : 300;

    __shared__ __align__(16) float sx[1200];
    __shared__ __align__(16) float sh[2][64];
    int tid = threadIdx.x;
    int u = tid >> 2, gt = tid & 3;
    int r = gt * 64 + u;

    ull rw[32];
#pragma unroll
    for (int jp = 0; jp < 32; jp++) rw[jp] = pack2(whh[r * 64 + 2 * jp], whh[r * 64 + 2 * jp + 1]);
    ull ri01 = pack2(wih[r * 4 + 0], wih[r * 4 + 1]);
    ull ri23 = pack2(wih[r * 4 + 2], wih[r * 4 + 3]);
    ull bgp = pack2(bih[r] + bhh[r], 0.f);

    for (int i = tid; i < T * 4; i += 256) sx[i] = xc[b * T * 4 + i];
    if (tid < 64) sh[0][tid] = 0.f;
    float c = 0.f;
    __syncthreads();

    const ulonglong2* sx2 = (const ulonglong2*)sx;
    unsigned lane = tid & 31;
    unsigned bse = lane & ~3u;

    for (int t = 0; t < T; t++) {
        const ulonglong2* sh2 = (const ulonglong2*)sh[t & 1];
        ulonglong2 xv = sx2[t];
        ull a0 = fma2(ri01, xv.x, bgp);
        ull a1 = fma2(ri23, xv.y, 0ULL);
        ull a2 = 0ULL, a3 = 0ULL;
#pragma unroll
        for (int q = 0; q < 8; q++) {
            ulonglong2 hv = sh2[q];
            ulonglong2 hw = sh2[q + 8];
            a0 = fma2(rw[2 * q],      hv.x, a0);
            a1 = fma2(rw[2 * q + 1],  hv.y, a1);
            a2 = fma2(rw[2 * q + 16], hw.x, a2);
            a3 = fma2(rw[2 * q + 17], hw.y, a3);
        }
        ull s = add2(add2(a0, a1), add2(a2, a3));
        float lo, hi;
        unpack2(s, lo, hi);
        float a = lo + hi;
        float act = (gt == 2) ? tanh_f(a) : sigm_f(a);
        float vi = __shfl_sync(0xffffffffu, act, bse | 0);
        float vf = __shfl_sync(0xffffffffu, act, bse | 1);
        float vg = __shfl_sync(0xffffffffu, act, bse | 2);
        float vo = __shfl_sync(0xffffffffu, act, bse | 3);
        c = fmaf(vf, c, vi * vg);
        if (gt == 0) sh[(t + 1) & 1][u] = vo * tanh_f(c);
        __syncthreads();
    }
    const float* hf = sh[T & 1];
    if (tid < 32) {
        float p = hf[tid] * wl[tid] + hf[tid + 32] * wl[tid + 32];
#pragma unroll
        for (int off = 16; off; off >>= 1) p += __shfl_down_sync(0xffffffffu, p, off);
        if (tid == 0) g_bo[b * 2 + br] = p + bl[0];
    }
}

// ---------------- K6: final head ----------------
__global__ void k_final(const float* __restrict__ w_rul, const float* __restrict__ b_rul,
                        float* __restrict__ out) {
    int b = threadIdx.x;
    if (b < 64) {
        float z = fmaf(w_rul[0], g_bo[b * 2], fmaf(w_rul[1], g_bo[b * 2 + 1], b_rul[0]));
        out[b] = 1.f / (1.f + expf(-z));
    }
}

// ---------------- host launch ----------------
extern "C" void kernel_launch(void* const* d_in, const int* in_sizes, int n_in,
                              void* d_out, int out_size) {
    const float* X      = (const float*)d_in[0];
    const float* w_dw   = (const float*)d_in[1];
    const float* b_dw   = (const float*)d_in[2];
    const float* w_pw   = (const float*)d_in[3];
    const float* b_pw   = (const float*)d_in[4];
    const float* w_c2   = (const float*)d_in[5];
    const float* b_c2   = (const float*)d_in[6];
    const float* w_sc0  = (const float*)d_in[7];
    const float* b_sc0  = (const float*)d_in[8];
    const float* w_ih0  = (const float*)d_in[9];
    const float* b_ih0  = (const float*)d_in[10];
    const float* w_hh0  = (const float*)d_in[11];
    const float* b_hh0  = (const float*)d_in[12];
    const float* w_lin0 = (const float*)d_in[13];
    const float* b_lin0 = (const float*)d_in[14];
    const float* w_sc1  = (const float*)d_in[15];
    const float* b_sc1  = (const float*)d_in[16];
    const float* w_ih1  = (const float*)d_in[17];
    const float* b_ih1  = (const float*)d_in[18];
    const float* w_hh1  = (const float*)d_in[19];
    const float* b_hh1  = (const float*)d_in[20];
    const float* w_lin1 = (const float*)d_in[21];
    const float* b_lin1 = (const float*)d_in[22];
    const float* w_rul  = (const float*)d_in[23];
    const float* b_rul  = (const float*)d_in[24];
    float* out = (float*)d_out;

    size_t shB = (size_t)(16 * 481 + 16 * 208) * 8 + (size_t)(32 * 177) * 4;   // 110848
    size_t shC = (size_t)(32 * 321 + 32 * 138) * 8;                            // 117504
    size_t shD = (size_t)(64 * 300) * sizeof(float);
    cudaFuncSetAttribute(k_conv1pool, cudaFuncAttributeMaxDynamicSharedMemorySize, (int)shB);
    cudaFuncSetAttribute(k_conv2, cudaFuncAttributeMaxDynamicSharedMemorySize, (int)shC);
    cudaFuncSetAttribute(k_smallconv, cudaFuncAttributeMaxDynamicSharedMemorySize, (int)shD);

    k_weff<<<70, 256>>>(w_dw, b_dw, w_pw, b_pw, w_c2);
    k_conv1pool<<<dim3(26, 64), 256, shB>>>(X);
    k_conv2<<<dim3(7, 64), 256, shC>>>(b_c2);
    k_adpool<<<dim3(64, 64), 128>>>();
    k_smallconv<<<64, 256, (size_t)(64 * 300) * sizeof(float)>>>(w_sc0, b_sc0, 0);
    k_smallconv<<<64, 256, (size_t)(64 * 100) * sizeof(float)>>>(w_sc1, b_sc1, 1);
    k_lstm<<<128, 256>>>(w_ih0, b_ih0, w_hh0, b_hh0, w_lin0, b_lin0,
                         w_ih1, b_ih1, w_hh1, b_hh1, w_lin1, b_lin1);
    k_final<<<1, 64>>>(w_rul, b_rul, out);
}